// round 1
// baseline (speedup 1.0000x reference)
#include <cuda_runtime.h>
#include <math_constants.h>
#include <cstddef>

// Problem constants
#define BB 4
#define TT 2048
#define DD 1024
#define HH 16
#define HD 64

// Scratch (device globals: allocation-guard-safe)
__device__ float g_q[(size_t)BB * HH * TT * HD];   // [B,H,T,HD]
__device__ float g_k[(size_t)BB * HH * TT * HD];
__device__ float g_v[(size_t)BB * HH * TT * HD];
__device__ float g_y[(size_t)BB * TT * DD];        // attention output [B,T,D]

// ---------------------------------------------------------------------------
// 128x128x16 SIMT fp32 GEMM, 256 threads, 8x8 per thread.
// SCATTER=1: epilogue scatters into g_q/g_k/g_v with head-major layout.
// SCATTER=0: plain row-major store into C0 with bias.
// ---------------------------------------------------------------------------
template <int SCATTER>
__global__ void gemm128(const float* __restrict__ A, const float* __restrict__ Bm,
                        const float* __restrict__ bias,
                        float* __restrict__ C0, float* __restrict__ C1, float* __restrict__ C2,
                        int M, int N, int K)
{
    __shared__ float As[16 * 132];   // A tile transposed: As[k*132 + m], padded
    __shared__ float Bs[16 * 128];   // B tile natural:    Bs[k*128 + n]

    const int tid = threadIdx.x;
    const int m0 = blockIdx.y * 128;
    const int n0 = blockIdx.x * 128;
    const int tm = tid >> 4;          // 0..15
    const int tn = tid & 15;          // 0..15
    const int arow = tid >> 2;        // 0..63
    const int acol = (tid & 3) << 2;  // 0,4,8,12
    const int brow = tid >> 5;        // 0..7
    const int bcol = (tid & 31) << 2; // 0..124

    float acc[8][8];
#pragma unroll
    for (int i = 0; i < 8; ++i)
#pragma unroll
        for (int j = 0; j < 8; ++j) acc[i][j] = 0.0f;

    for (int k0 = 0; k0 < K; k0 += 16) {
#pragma unroll
        for (int p = 0; p < 2; ++p) {
            float4 av = *(const float4*)(A + (size_t)(m0 + arow + p * 64) * K + k0 + acol);
            As[(acol + 0) * 132 + arow + p * 64] = av.x;
            As[(acol + 1) * 132 + arow + p * 64] = av.y;
            As[(acol + 2) * 132 + arow + p * 64] = av.z;
            As[(acol + 3) * 132 + arow + p * 64] = av.w;
        }
#pragma unroll
        for (int p = 0; p < 2; ++p) {
            *(float4*)(Bs + (brow + p * 8) * 128 + bcol) =
                *(const float4*)(Bm + (size_t)(k0 + brow + p * 8) * N + n0 + bcol);
        }
        __syncthreads();

#pragma unroll 8
        for (int kk = 0; kk < 16; ++kk) {
            float a[8], b[8];
            *(float4*)&a[0] = *(float4*)(As + kk * 132 + tm * 8);
            *(float4*)&a[4] = *(float4*)(As + kk * 132 + tm * 8 + 4);
            *(float4*)&b[0] = *(float4*)(Bs + kk * 128 + tn * 8);
            *(float4*)&b[4] = *(float4*)(Bs + kk * 128 + tn * 8 + 4);
#pragma unroll
            for (int i = 0; i < 8; ++i)
#pragma unroll
                for (int j = 0; j < 8; ++j)
                    acc[i][j] = fmaf(a[i], b[j], acc[i][j]);
        }
        __syncthreads();
    }

    if (SCATTER) {
        // QKV epilogue: n in [0,3072): which = n/1024, head = (n%1024)/64, d = n%64
        // dst layout [B,H,T,HD]
#pragma unroll
        for (int i = 0; i < 8; ++i) {
            int m = m0 + tm * 8 + i;
            int bb = m >> 11;        // /2048
            int t = m & 2047;
#pragma unroll
            for (int j = 0; j < 8; ++j) {
                int n = n0 + tn * 8 + j;
                float v = acc[i][j] + bias[n];
                int which = n >> 10;
                int c = n & 1023;
                int h = c >> 6;
                int d = c & 63;
                float* dst = (which == 0) ? C0 : ((which == 1) ? C1 : C2);
                dst[(((size_t)bb * HH + h) * TT + t) * HD + d] = v;
            }
        }
    } else {
#pragma unroll
        for (int i = 0; i < 8; ++i) {
            size_t row = (size_t)(m0 + tm * 8 + i) * N;
#pragma unroll
            for (int j = 0; j < 8; j += 4) {
                int n = n0 + tn * 8 + j;
                float4 v;
                v.x = acc[i][j + 0] + bias[n + 0];
                v.y = acc[i][j + 1] + bias[n + 1];
                v.z = acc[i][j + 2] + bias[n + 2];
                v.w = acc[i][j + 3] + bias[n + 3];
                *(float4*)(C0 + row + n) = v;
            }
        }
    }
}

// ---------------------------------------------------------------------------
// Flash attention, fp32, 64x64 tiles, causal. 256 threads = 16x16 grid of 4x4.
// exp2-domain softmax: scale*log2(e) folded into Q at load time.
// ---------------------------------------------------------------------------
__global__ void attn_kernel(const float* __restrict__ gq, const float* __restrict__ gk,
                            const float* __restrict__ gv, float* __restrict__ gy)
{
    extern __shared__ float sm[];
    float* Qs = sm;                  // [64][68] transposed: Qs[d*68 + i]
    float* Ks = Qs + 64 * 68;        // [64][68] transposed: Ks[d*68 + j]
    float* Vs = Ks + 64 * 68;        // [64][64] natural:    Vs[j*64 + d]
    float* Ps = Vs + 64 * 64;        // [64][64]

    const int qt = blockIdx.x;       // q tile index (0..31)
    const int bh = blockIdx.y;       // b*H + h     (0..63)
    const int q0 = qt * 64;
    const size_t base = (size_t)bh * TT * HD;
    const float* Q = gq + base;
    const float* K = gk + base;
    const float* V = gv + base;

    const int tid = threadIdx.x;
    const int ty = tid >> 4;         // 0..15 -> rows ty*4..ty*4+3
    const int tx = tid & 15;         // 0..15 -> cols tx*4..tx*4+3

    const float kScale = 0.125f * 1.4426950408889634f;  // 1/sqrt(64) * log2(e)
    for (int idx = tid; idx < 64 * 64; idx += 256) {
        int i = idx >> 6, d = idx & 63;
        Qs[d * 68 + i] = Q[(size_t)(q0 + i) * HD + d] * kScale;
    }

    float o[4][4];
    float m_i[4], l_i[4];
#pragma unroll
    for (int r = 0; r < 4; ++r) {
        m_i[r] = -CUDART_INF_F;
        l_i[r] = 0.0f;
#pragma unroll
        for (int c = 0; c < 4; ++c) o[r][c] = 0.0f;
    }

    for (int kt = 0; kt <= qt; ++kt) {
        const int k0 = kt * 64;
        __syncthreads();   // previous PV reads done (and Qs visible on first iter)
        for (int idx = tid; idx < 64 * 64; idx += 256) {
            int j = idx >> 6, d = idx & 63;
            Ks[d * 68 + j] = K[(size_t)(k0 + j) * HD + d];
            Vs[idx] = V[(size_t)k0 * HD + idx];
        }
        __syncthreads();

        // S = Q K^T (already in log2-domain units)
        float s[4][4];
#pragma unroll
        for (int r = 0; r < 4; ++r)
#pragma unroll
            for (int c = 0; c < 4; ++c) s[r][c] = 0.0f;

#pragma unroll 8
        for (int d = 0; d < 64; ++d) {
            float4 qv = *(float4*)(Qs + d * 68 + ty * 4);
            float4 kv = *(float4*)(Ks + d * 68 + tx * 4);
            float qa[4] = {qv.x, qv.y, qv.z, qv.w};
            float ka[4] = {kv.x, kv.y, kv.z, kv.w};
#pragma unroll
            for (int r = 0; r < 4; ++r)
#pragma unroll
                for (int c = 0; c < 4; ++c)
                    s[r][c] = fmaf(qa[r], ka[c], s[r][c]);
        }

        if (kt == qt) {
#pragma unroll
            for (int r = 0; r < 4; ++r)
#pragma unroll
                for (int c = 0; c < 4; ++c)
                    if (tx * 4 + c > ty * 4 + r) s[r][c] = -CUDART_INF_F;
        }

        // online softmax update
#pragma unroll
        for (int r = 0; r < 4; ++r) {
            float mx = fmaxf(fmaxf(s[r][0], s[r][1]), fmaxf(s[r][2], s[r][3]));
#pragma unroll
            for (int off = 8; off; off >>= 1)
                mx = fmaxf(mx, __shfl_xor_sync(0xffffffffu, mx, off));
            float mnew = fmaxf(m_i[r], mx);
            float alpha = exp2f(m_i[r] - mnew);
            float rs = 0.0f;
#pragma unroll
            for (int c = 0; c < 4; ++c) {
                s[r][c] = exp2f(s[r][c] - mnew);
                rs += s[r][c];
            }
#pragma unroll
            for (int off = 8; off; off >>= 1)
                rs += __shfl_xor_sync(0xffffffffu, rs, off);
            l_i[r] = l_i[r] * alpha + rs;
            m_i[r] = mnew;
#pragma unroll
            for (int c = 0; c < 4; ++c) o[r][c] *= alpha;
        }

        // stage P into smem for the PV GEMM
#pragma unroll
        for (int r = 0; r < 4; ++r) {
            float4 pv;
            pv.x = s[r][0]; pv.y = s[r][1]; pv.z = s[r][2]; pv.w = s[r][3];
            *(float4*)(Ps + (ty * 4 + r) * 64 + tx * 4) = pv;
        }
        __syncthreads();

        // O += P @ V
#pragma unroll 4
        for (int j = 0; j < 64; j += 4) {
            float pr[4][4];
#pragma unroll
            for (int r = 0; r < 4; ++r)
                *(float4*)pr[r] = *(float4*)(Ps + (ty * 4 + r) * 64 + j);
#pragma unroll
            for (int jj = 0; jj < 4; ++jj) {
                float4 vv = *(float4*)(Vs + (j + jj) * 64 + tx * 4);
#pragma unroll
                for (int r = 0; r < 4; ++r) {
                    o[r][0] = fmaf(pr[r][jj], vv.x, o[r][0]);
                    o[r][1] = fmaf(pr[r][jj], vv.y, o[r][1]);
                    o[r][2] = fmaf(pr[r][jj], vv.z, o[r][2]);
                    o[r][3] = fmaf(pr[r][jj], vv.w, o[r][3]);
                }
            }
        }
    }

    // epilogue: normalize and write y[B,T,D] with column h*64 + d
    const int b = bh >> 4;
    const int h = bh & 15;
#pragma unroll
    for (int r = 0; r < 4; ++r) {
        float inv = 1.0f / l_i[r];
        int t = q0 + ty * 4 + r;
        float4 ov;
        ov.x = o[r][0] * inv;
        ov.y = o[r][1] * inv;
        ov.z = o[r][2] * inv;
        ov.w = o[r][3] * inv;
        *(float4*)(gy + ((size_t)b * TT + t) * DD + h * 64 + tx * 4) = ov;
    }
}

// ---------------------------------------------------------------------------
// Launch: QKV GEMM -> flash attention -> output GEMM
// ---------------------------------------------------------------------------
extern "C" void kernel_launch(void* const* d_in, const int* in_sizes, int n_in,
                              void* d_out, int out_size)
{
    (void)in_sizes; (void)n_in; (void)out_size;
    const float* x     = (const float*)d_in[0];
    // d_in[1] = mask (causal tril, constant) — implemented analytically
    const float* w_qkv = (const float*)d_in[2];
    const float* b_qkv = (const float*)d_in[3];
    const float* w_out = (const float*)d_in[4];
    const float* b_out = (const float*)d_in[5];
    float* out = (float*)d_out;

    float *gq, *gk, *gv, *gy;
    cudaGetSymbolAddress((void**)&gq, g_q);
    cudaGetSymbolAddress((void**)&gk, g_k);
    cudaGetSymbolAddress((void**)&gv, g_v);
    cudaGetSymbolAddress((void**)&gy, g_y);

    const int ATTN_SMEM = (64 * 68 * 2 + 64 * 64 * 2) * (int)sizeof(float); // 67584
    cudaFuncSetAttribute(attn_kernel, cudaFuncAttributeMaxDynamicSharedMemorySize, ATTN_SMEM);

    // 1) QKV projection with head-major scatter: [8192,1024] @ [1024,3072]
    {
        dim3 grid(3072 / 128, 8192 / 128);
        gemm128<1><<<grid, 256>>>(x, w_qkv, b_qkv, gq, gk, gv, BB * TT, 3 * DD, DD);
    }

    // 2) causal flash attention per (q-tile, b*h)
    {
        dim3 grid(TT / 64, BB * HH);
        attn_kernel<<<grid, 256, ATTN_SMEM>>>(gq, gk, gv, gy);
    }

    // 3) output projection: [8192,1024] @ [1024,1024] + b_out
    {
        dim3 grid(1024 / 128, 8192 / 128);
        gemm128<0><<<grid, 256>>>(gy, w_out, b_out, out, nullptr, nullptr, BB * TT, DD, DD);
    }
}

// round 3
// speedup vs baseline: 1.6146x; 1.6146x over previous
#include <cuda_runtime.h>
#include <cuda_bf16.h>
#include <math_constants.h>
#include <cstddef>
#include <cstdint>

// Problem constants
#define BB 4
#define TT 2048
#define DD 1024
#define HH 16
#define HD 64

// ---------------------------------------------------------------------------
// Scratch (device globals: allocation-guard-safe)
// ---------------------------------------------------------------------------
__device__ float g_q[(size_t)BB * HH * TT * HD];   // [B,H,T,HD]
__device__ float g_k[(size_t)BB * HH * TT * HD];
__device__ float g_v[(size_t)BB * HH * TT * HD];
__device__ float g_y[(size_t)BB * TT * DD];        // attention output [B,T,D]

__device__ __nv_bfloat16 g_xhi[(size_t)BB * TT * DD];
__device__ __nv_bfloat16 g_xlo[(size_t)BB * TT * DD];
__device__ __nv_bfloat16 g_wqhi[(size_t)3 * DD * DD];   // w_qkv^T [3072,1024]
__device__ __nv_bfloat16 g_wqlo[(size_t)3 * DD * DD];
__device__ __nv_bfloat16 g_wohi[(size_t)DD * DD];        // w_out^T [1024,1024]
__device__ __nv_bfloat16 g_wolo[(size_t)DD * DD];
__device__ __nv_bfloat16 g_yhi[(size_t)BB * TT * DD];
__device__ __nv_bfloat16 g_ylo[(size_t)BB * TT * DD];

#define SWZ128(o) ((o) ^ (((o) >> 3) & 0x70))

// ---------------------------------------------------------------------------
// mma.sync helpers (baseline PTX ISA — compiles under compute_103)
// ---------------------------------------------------------------------------
__device__ __forceinline__ void ldsm_x4(uint32_t& r0, uint32_t& r1, uint32_t& r2, uint32_t& r3,
                                        uint32_t addr) {
    asm volatile("ldmatrix.sync.aligned.m8n8.x4.shared.b16 {%0,%1,%2,%3}, [%4];"
                 : "=r"(r0), "=r"(r1), "=r"(r2), "=r"(r3) : "r"(addr));
}

__device__ __forceinline__ void mma_bf16(float* d, const uint32_t* a, const uint32_t* b) {
    asm volatile(
        "mma.sync.aligned.m16n8k16.row.col.f32.bf16.bf16.f32 "
        "{%0,%1,%2,%3}, {%4,%5,%6,%7}, {%8,%9}, {%0,%1,%2,%3};"
        : "+f"(d[0]), "+f"(d[1]), "+f"(d[2]), "+f"(d[3])
        : "r"(a[0]), "r"(a[1]), "r"(a[2]), "r"(a[3]), "r"(b[0]), "r"(b[1]));
}

// ---------------------------------------------------------------------------
// Split fp32 -> (bf16 hi, bf16 lo). One thread per 4 elems.
// ---------------------------------------------------------------------------
__global__ void split_kernel(const float* __restrict__ x,
                             __nv_bfloat16* __restrict__ hi, __nv_bfloat16* __restrict__ lo)
{
    size_t i = ((size_t)blockIdx.x * blockDim.x + threadIdx.x) * 4;
    float4 v = *(const float4*)(x + i);
    float a[4] = {v.x, v.y, v.z, v.w};
    __nv_bfloat16 h[4], l[4];
#pragma unroll
    for (int j = 0; j < 4; ++j) {
        h[j] = __float2bfloat16(a[j]);
        l[j] = __float2bfloat16(a[j] - __bfloat162float(h[j]));
    }
    *(__nv_bfloat162*)(hi + i)     = __nv_bfloat162(h[0], h[1]);
    *(__nv_bfloat162*)(hi + i + 2) = __nv_bfloat162(h[2], h[3]);
    *(__nv_bfloat162*)(lo + i)     = __nv_bfloat162(l[0], l[1]);
    *(__nv_bfloat162*)(lo + i + 2) = __nv_bfloat162(l[2], l[3]);
}

// Transpose + split: w [K=1024, N] -> wT hi/lo [N, 1024]
__global__ void splitT_kernel(const float* __restrict__ w,
                              __nv_bfloat16* __restrict__ hi, __nv_bfloat16* __restrict__ lo, int N)
{
    size_t idx = (size_t)blockIdx.x * blockDim.x + threadIdx.x;
    int k = (int)(idx & 1023);
    size_t n = idx >> 10;
    float v = w[(size_t)k * N + n];
    __nv_bfloat16 h = __float2bfloat16(v);
    hi[idx] = h;
    lo[idx] = __float2bfloat16(v - __bfloat162float(h));
}

// ---------------------------------------------------------------------------
// mma.sync bf16 split GEMM: C[M,NW] = A[M,1024] @ W^T (3-term emulation).
// CTA tile 128x128, 8 warps (2x4), warp tile 64x32, K-chunk 64, SW128 smem.
// SCATTER=1: QKV epilogue scatters into g_q/g_k/g_v ([B,H,T,HD]).
// ---------------------------------------------------------------------------
#define SA_HI 0
#define SA_LO 16384
#define SB_HI 32768
#define SB_LO 49152
#define GEMM_SMEM 65536

template <int SCATTER>
__global__ void __launch_bounds__(256, 2) mma_gemm(
    const __nv_bfloat16* __restrict__ Ahi, const __nv_bfloat16* __restrict__ Alo,
    const __nv_bfloat16* __restrict__ Bhi, const __nv_bfloat16* __restrict__ Blo,
    const float* __restrict__ bias,
    float* __restrict__ C0, float* __restrict__ C1, float* __restrict__ C2,
    int NW)
{
    extern __shared__ char smem[];
    const uint32_t sbase = (uint32_t)__cvta_generic_to_shared(smem);
    const int tid = threadIdx.x;
    const int w = tid >> 5;
    const int l = tid & 31;
    const int wm = w >> 2;           // 0..1
    const int wn = w & 3;            // 0..3
    const int m0 = blockIdx.y * 128;
    const int n0 = blockIdx.x * 128;

    // loader lane mapping: 8 threads cover one 128B row
    const int lr = tid >> 3;         // 0..31
    const int lc = tid & 7;          // 16B column

    // ldmatrix lane mapping
    const int sub = l >> 3;                       // 0..3
    const int a_row_in = ((sub & 1) << 3) + (l & 7);   // row within 16-row tile
    const int a_kb = (sub >> 1) << 4;                  // 0 or 16 bytes
    const int b_j2 = l >> 4;                      // 0..1 (n-tile pair member)
    const int b_kb = ((l >> 3) & 1) << 4;         // 0 or 16 bytes
    const int b_row_in = l & 7;

    float acc[4][4][4];
#pragma unroll
    for (int i = 0; i < 4; ++i)
#pragma unroll
        for (int j = 0; j < 4; ++j)
#pragma unroll
            for (int r = 0; r < 4; ++r) acc[i][j][r] = 0.0f;

    for (int kc = 0; kc < 1024; kc += 64) {
        __syncthreads();
#pragma unroll
        for (int p = 0; p < 4; ++p) {
            int r = lr + p * 32;
            uint32_t so = SWZ128((uint32_t)(r * 128 + lc * 16));
            size_t goA = (size_t)(m0 + r) * 1024 + kc + lc * 8;
            size_t goB = (size_t)(n0 + r) * 1024 + kc + lc * 8;
            *(uint4*)(smem + SA_HI + so) = *(const uint4*)(Ahi + goA);
            *(uint4*)(smem + SA_LO + so) = *(const uint4*)(Alo + goA);
            *(uint4*)(smem + SB_HI + so) = *(const uint4*)(Bhi + goB);
            *(uint4*)(smem + SB_LO + so) = *(const uint4*)(Blo + goB);
        }
        __syncthreads();

#pragma unroll
        for (int ks = 0; ks < 4; ++ks) {
            const int kb = ks * 32;   // byte offset of this k16 step

            // fragment smem offsets (same swizzled offset for hi and lo)
            uint32_t aoff[4], boff[2];
#pragma unroll
            for (int i = 0; i < 4; ++i) {
                int row = wm * 64 + i * 16 + a_row_in;
                aoff[i] = SWZ128((uint32_t)(row * 128 + kb + a_kb));
            }
#pragma unroll
            for (int jp = 0; jp < 2; ++jp) {
                int row = wn * 32 + (jp * 2 + b_j2) * 8 + b_row_in;
                boff[jp] = SWZ128((uint32_t)(row * 128 + kb + b_kb));
            }

            uint32_t ah[4][4], al[4][4], bh[4][2], bl[4][2];
#pragma unroll
            for (int i = 0; i < 4; ++i) {
                ldsm_x4(ah[i][0], ah[i][1], ah[i][2], ah[i][3], sbase + SA_HI + aoff[i]);
                ldsm_x4(al[i][0], al[i][1], al[i][2], al[i][3], sbase + SA_LO + aoff[i]);
            }
#pragma unroll
            for (int jp = 0; jp < 2; ++jp) {
                ldsm_x4(bh[jp * 2][0], bh[jp * 2][1], bh[jp * 2 + 1][0], bh[jp * 2 + 1][1],
                        sbase + SB_HI + boff[jp]);
                ldsm_x4(bl[jp * 2][0], bl[jp * 2][1], bl[jp * 2 + 1][0], bl[jp * 2 + 1][1],
                        sbase + SB_LO + boff[jp]);
            }

#pragma unroll
            for (int i = 0; i < 4; ++i)
#pragma unroll
                for (int j = 0; j < 4; ++j) {
                    mma_bf16(acc[i][j], ah[i], bh[j]);
                    mma_bf16(acc[i][j], ah[i], bl[j]);
                    mma_bf16(acc[i][j], al[i], bh[j]);
                }
        }
    }

    // epilogue
    const int gr = l >> 2;
    const int gc = (l & 3) << 1;
#pragma unroll
    for (int i = 0; i < 4; ++i) {
        int mrow = m0 + wm * 64 + i * 16 + gr;
#pragma unroll
        for (int j = 0; j < 4; ++j) {
            int n = n0 + wn * 32 + j * 8 + gc;
            float2 bv = *(const float2*)(bias + n);
            float2 v0, v1;
            v0.x = acc[i][j][0] + bv.x;
            v0.y = acc[i][j][1] + bv.y;
            v1.x = acc[i][j][2] + bv.x;
            v1.y = acc[i][j][3] + bv.y;
            if (SCATTER) {
                int bb = mrow >> 11;
                int t = mrow & 2047;
                int which = n >> 10;
                int c = n & 1023;
                int h = c >> 6;
                int d = c & 63;
                float* dst = (which == 0) ? C0 : ((which == 1) ? C1 : C2);
                float* ptr = dst + (((size_t)bb * HH + h) * TT + t) * HD + d;
                *(float2*)ptr = v0;
                *(float2*)(ptr + 8 * HD) = v1;   // row t+8
            } else {
                float* ptr = C0 + (size_t)mrow * NW + n;
                *(float2*)ptr = v0;
                *(float2*)(ptr + 8 * (size_t)NW) = v1;
            }
        }
    }
}

// ---------------------------------------------------------------------------
// Flash attention, fp32, 64x64 tiles, causal (unchanged, known-good).
// ---------------------------------------------------------------------------
__global__ void attn_kernel(const float* __restrict__ gq, const float* __restrict__ gk,
                            const float* __restrict__ gv, float* __restrict__ gy)
{
    extern __shared__ float sm[];
    float* Qs = sm;                  // [64][68] transposed
    float* Ks = Qs + 64 * 68;        // [64][68] transposed
    float* Vs = Ks + 64 * 68;        // [64][64]
    float* Ps = Vs + 64 * 64;        // [64][64]

    const int qt = blockIdx.x;
    const int bh = blockIdx.y;
    const int q0 = qt * 64;
    const size_t base = (size_t)bh * TT * HD;
    const float* Q = gq + base;
    const float* K = gk + base;
    const float* V = gv + base;

    const int tid = threadIdx.x;
    const int ty = tid >> 4;
    const int tx = tid & 15;

    const float kScale = 0.125f * 1.4426950408889634f;
    for (int idx = tid; idx < 64 * 64; idx += 256) {
        int i = idx >> 6, d = idx & 63;
        Qs[d * 68 + i] = Q[(size_t)(q0 + i) * HD + d] * kScale;
    }

    float o[4][4];
    float m_i[4], l_i[4];
#pragma unroll
    for (int r = 0; r < 4; ++r) {
        m_i[r] = -CUDART_INF_F;
        l_i[r] = 0.0f;
#pragma unroll
        for (int c = 0; c < 4; ++c) o[r][c] = 0.0f;
    }

    for (int kt = 0; kt <= qt; ++kt) {
        const int k0 = kt * 64;
        __syncthreads();
        for (int idx = tid; idx < 64 * 64; idx += 256) {
            int j = idx >> 6, d = idx & 63;
            Ks[d * 68 + j] = K[(size_t)(k0 + j) * HD + d];
            Vs[idx] = V[(size_t)k0 * HD + idx];
        }
        __syncthreads();

        float s[4][4];
#pragma unroll
        for (int r = 0; r < 4; ++r)
#pragma unroll
            for (int c = 0; c < 4; ++c) s[r][c] = 0.0f;

#pragma unroll 8
        for (int d = 0; d < 64; ++d) {
            float4 qv = *(float4*)(Qs + d * 68 + ty * 4);
            float4 kv = *(float4*)(Ks + d * 68 + tx * 4);
            float qa[4] = {qv.x, qv.y, qv.z, qv.w};
            float ka[4] = {kv.x, kv.y, kv.z, kv.w};
#pragma unroll
            for (int r = 0; r < 4; ++r)
#pragma unroll
                for (int c = 0; c < 4; ++c)
                    s[r][c] = fmaf(qa[r], ka[c], s[r][c]);
        }

        if (kt == qt) {
#pragma unroll
            for (int r = 0; r < 4; ++r)
#pragma unroll
                for (int c = 0; c < 4; ++c)
                    if (tx * 4 + c > ty * 4 + r) s[r][c] = -CUDART_INF_F;
        }

#pragma unroll
        for (int r = 0; r < 4; ++r) {
            float mx = fmaxf(fmaxf(s[r][0], s[r][1]), fmaxf(s[r][2], s[r][3]));
#pragma unroll
            for (int off = 8; off; off >>= 1)
                mx = fmaxf(mx, __shfl_xor_sync(0xffffffffu, mx, off));
            float mnew = fmaxf(m_i[r], mx);
            float alpha = exp2f(m_i[r] - mnew);
            float rs = 0.0f;
#pragma unroll
            for (int c = 0; c < 4; ++c) {
                s[r][c] = exp2f(s[r][c] - mnew);
                rs += s[r][c];
            }
#pragma unroll
            for (int off = 8; off; off >>= 1)
                rs += __shfl_xor_sync(0xffffffffu, rs, off);
            l_i[r] = l_i[r] * alpha + rs;
            m_i[r] = mnew;
#pragma unroll
            for (int c = 0; c < 4; ++c) o[r][c] *= alpha;
        }

#pragma unroll
        for (int r = 0; r < 4; ++r) {
            float4 pv;
            pv.x = s[r][0]; pv.y = s[r][1]; pv.z = s[r][2]; pv.w = s[r][3];
            *(float4*)(Ps + (ty * 4 + r) * 64 + tx * 4) = pv;
        }
        __syncthreads();

#pragma unroll 4
        for (int j = 0; j < 64; j += 4) {
            float pr[4][4];
#pragma unroll
            for (int r = 0; r < 4; ++r)
                *(float4*)pr[r] = *(float4*)(Ps + (ty * 4 + r) * 64 + j);
#pragma unroll
            for (int jj = 0; jj < 4; ++jj) {
                float4 vv = *(float4*)(Vs + (j + jj) * 64 + tx * 4);
#pragma unroll
                for (int r = 0; r < 4; ++r) {
                    o[r][0] = fmaf(pr[r][jj], vv.x, o[r][0]);
                    o[r][1] = fmaf(pr[r][jj], vv.y, o[r][1]);
                    o[r][2] = fmaf(pr[r][jj], vv.z, o[r][2]);
                    o[r][3] = fmaf(pr[r][jj], vv.w, o[r][3]);
                }
            }
        }
    }

    const int b = bh >> 4;
    const int h = bh & 15;
#pragma unroll
    for (int r = 0; r < 4; ++r) {
        float inv = 1.0f / l_i[r];
        int t = q0 + ty * 4 + r;
        float4 ov;
        ov.x = o[r][0] * inv;
        ov.y = o[r][1] * inv;
        ov.z = o[r][2] * inv;
        ov.w = o[r][3] * inv;
        *(float4*)(gy + ((size_t)b * TT + t) * DD + h * 64 + tx * 4) = ov;
    }
}

// ---------------------------------------------------------------------------
// Launch pipeline
// ---------------------------------------------------------------------------
extern "C" void kernel_launch(void* const* d_in, const int* in_sizes, int n_in,
                              void* d_out, int out_size)
{
    (void)in_sizes; (void)n_in; (void)out_size;
    const float* x     = (const float*)d_in[0];
    // d_in[1] = causal mask, handled analytically
    const float* w_qkv = (const float*)d_in[2];
    const float* b_qkv = (const float*)d_in[3];
    const float* w_out = (const float*)d_in[4];
    const float* b_out = (const float*)d_in[5];
    float* out = (float*)d_out;

    float *gq, *gk, *gv, *gy;
    __nv_bfloat16 *xhi, *xlo, *wqhi, *wqlo, *wohi, *wolo, *yhi, *ylo;
    cudaGetSymbolAddress((void**)&gq, g_q);
    cudaGetSymbolAddress((void**)&gk, g_k);
    cudaGetSymbolAddress((void**)&gv, g_v);
    cudaGetSymbolAddress((void**)&gy, g_y);
    cudaGetSymbolAddress((void**)&xhi, g_xhi);
    cudaGetSymbolAddress((void**)&xlo, g_xlo);
    cudaGetSymbolAddress((void**)&wqhi, g_wqhi);
    cudaGetSymbolAddress((void**)&wqlo, g_wqlo);
    cudaGetSymbolAddress((void**)&wohi, g_wohi);
    cudaGetSymbolAddress((void**)&wolo, g_wolo);
    cudaGetSymbolAddress((void**)&yhi, g_yhi);
    cudaGetSymbolAddress((void**)&ylo, g_ylo);

    cudaFuncSetAttribute(mma_gemm<1>, cudaFuncAttributeMaxDynamicSharedMemorySize, GEMM_SMEM);
    cudaFuncSetAttribute(mma_gemm<0>, cudaFuncAttributeMaxDynamicSharedMemorySize, GEMM_SMEM);
    const int ATTN_SMEM = (64 * 68 * 2 + 64 * 64 * 2) * (int)sizeof(float);
    cudaFuncSetAttribute(attn_kernel, cudaFuncAttributeMaxDynamicSharedMemorySize, ATTN_SMEM);

    const size_t MX = (size_t)BB * TT * DD;  // 8388608

    // split inputs
    split_kernel<<<(unsigned)(MX / 4 / 256), 256>>>(x, xhi, xlo);
    splitT_kernel<<<(unsigned)(3 * DD * DD / 256), 256>>>(w_qkv, wqhi, wqlo, 3 * DD);
    splitT_kernel<<<(unsigned)(DD * DD / 256), 256>>>(w_out, wohi, wolo, DD);

    // 1) QKV projection: [8192,1024] x [3072,1024]^T, scatter into q/k/v
    {
        dim3 grid(3 * DD / 128, BB * TT / 128);   // (24, 64)
        mma_gemm<1><<<grid, 256, GEMM_SMEM>>>(xhi, xlo, wqhi, wqlo, b_qkv, gq, gk, gv, 3 * DD);
    }

    // 2) causal flash attention
    {
        dim3 grid(TT / 64, BB * HH);
        attn_kernel<<<grid, 256, ATTN_SMEM>>>(gq, gk, gv, gy);
    }

    // 3) split y, then output projection
    split_kernel<<<(unsigned)(MX / 4 / 256), 256>>>(gy, yhi, ylo);
    {
        dim3 grid(DD / 128, BB * TT / 128);       // (8, 64)
        mma_gemm<0><<<grid, 256, GEMM_SMEM>>>(yhi, ylo, wohi, wolo, b_out, out, nullptr, nullptr, DD);
    }
}

// round 4
// speedup vs baseline: 2.9344x; 1.8174x over previous
#include <cuda_runtime.h>
#include <cuda_bf16.h>
#include <math_constants.h>
#include <cstddef>
#include <cstdint>

// Problem constants
#define BB 4
#define TT 2048
#define DD 1024
#define HH 16
#define HD 64

#define KSCALE (0.125f * 1.4426950408889634f)   // 1/sqrt(64) * log2(e)

// ---------------------------------------------------------------------------
// Scratch (device globals: allocation-guard-safe)
// ---------------------------------------------------------------------------
__device__ __nv_bfloat16 g_qhi[(size_t)BB * HH * TT * HD];  // [B,H,T,HD], pre-scaled
__device__ __nv_bfloat16 g_qlo[(size_t)BB * HH * TT * HD];
__device__ __nv_bfloat16 g_khi[(size_t)BB * HH * TT * HD];
__device__ __nv_bfloat16 g_klo[(size_t)BB * HH * TT * HD];
__device__ __nv_bfloat16 g_vhi[(size_t)BB * HH * TT * HD];
__device__ __nv_bfloat16 g_vlo[(size_t)BB * HH * TT * HD];

__device__ __nv_bfloat16 g_xhi[(size_t)BB * TT * DD];
__device__ __nv_bfloat16 g_xlo[(size_t)BB * TT * DD];
__device__ __nv_bfloat16 g_wqhi[(size_t)3 * DD * DD];   // w_qkv^T [3072,1024]
__device__ __nv_bfloat16 g_wqlo[(size_t)3 * DD * DD];
__device__ __nv_bfloat16 g_wohi[(size_t)DD * DD];        // w_out^T [1024,1024]
__device__ __nv_bfloat16 g_wolo[(size_t)DD * DD];
__device__ __nv_bfloat16 g_yhi[(size_t)BB * TT * DD];    // attention out, split
__device__ __nv_bfloat16 g_ylo[(size_t)BB * TT * DD];

#define SWZ128(o) ((o) ^ (((o) >> 3) & 0x70))

// ---------------------------------------------------------------------------
// mma.sync helpers (baseline PTX ISA — compiles under compute_103)
// ---------------------------------------------------------------------------
__device__ __forceinline__ void ldsm_x4(uint32_t& r0, uint32_t& r1, uint32_t& r2, uint32_t& r3,
                                        uint32_t addr) {
    asm volatile("ldmatrix.sync.aligned.m8n8.x4.shared.b16 {%0,%1,%2,%3}, [%4];"
                 : "=r"(r0), "=r"(r1), "=r"(r2), "=r"(r3) : "r"(addr));
}
__device__ __forceinline__ void ldsm_x4_t(uint32_t& r0, uint32_t& r1, uint32_t& r2, uint32_t& r3,
                                          uint32_t addr) {
    asm volatile("ldmatrix.sync.aligned.m8n8.x4.trans.shared.b16 {%0,%1,%2,%3}, [%4];"
                 : "=r"(r0), "=r"(r1), "=r"(r2), "=r"(r3) : "r"(addr));
}
__device__ __forceinline__ void mma_bf16(float* d, const uint32_t* a, const uint32_t* b) {
    asm volatile(
        "mma.sync.aligned.m16n8k16.row.col.f32.bf16.bf16.f32 "
        "{%0,%1,%2,%3}, {%4,%5,%6,%7}, {%8,%9}, {%0,%1,%2,%3};"
        : "+f"(d[0]), "+f"(d[1]), "+f"(d[2]), "+f"(d[3])
        : "r"(a[0]), "r"(a[1]), "r"(a[2]), "r"(a[3]), "r"(b[0]), "r"(b[1]));
}
__device__ __forceinline__ uint32_t packbf(float a, float b) {
    __nv_bfloat162 t = __floats2bfloat162_rn(a, b);
    return *(uint32_t*)&t;
}

// ---------------------------------------------------------------------------
// Split fp32 -> (bf16 hi, bf16 lo). One thread per 4 elems.
// ---------------------------------------------------------------------------
__global__ void split_kernel(const float* __restrict__ x,
                             __nv_bfloat16* __restrict__ hi, __nv_bfloat16* __restrict__ lo)
{
    size_t i = ((size_t)blockIdx.x * blockDim.x + threadIdx.x) * 4;
    float4 v = *(const float4*)(x + i);
    float a[4] = {v.x, v.y, v.z, v.w};
    __nv_bfloat16 h[4], l[4];
#pragma unroll
    for (int j = 0; j < 4; ++j) {
        h[j] = __float2bfloat16(a[j]);
        l[j] = __float2bfloat16(a[j] - __bfloat162float(h[j]));
    }
    *(__nv_bfloat162*)(hi + i)     = __nv_bfloat162(h[0], h[1]);
    *(__nv_bfloat162*)(hi + i + 2) = __nv_bfloat162(h[2], h[3]);
    *(__nv_bfloat162*)(lo + i)     = __nv_bfloat162(l[0], l[1]);
    *(__nv_bfloat162*)(lo + i + 2) = __nv_bfloat162(l[2], l[3]);
}

// Transpose + split: w [K=1024, N] -> wT hi/lo [N, 1024]
__global__ void splitT_kernel(const float* __restrict__ w,
                              __nv_bfloat16* __restrict__ hi, __nv_bfloat16* __restrict__ lo, int N)
{
    size_t idx = (size_t)blockIdx.x * blockDim.x + threadIdx.x;
    int k = (int)(idx & 1023);
    size_t n = idx >> 10;
    float v = w[(size_t)k * N + n];
    __nv_bfloat16 h = __float2bfloat16(v);
    hi[idx] = h;
    lo[idx] = __float2bfloat16(v - __bfloat162float(h));
}

// ---------------------------------------------------------------------------
// Shared GEMM mainloop pieces (CTA 128x128, 8 warps 2x4, K-chunk 64, SW128)
// ---------------------------------------------------------------------------
#define SA_HI 0
#define SA_LO 16384
#define SB_HI 32768
#define SB_LO 49152
#define GEMM_SMEM 65536

#define GEMM_MAINLOOP(Ahi, Alo, Bhi, Blo)                                                \
    for (int kc = 0; kc < 1024; kc += 64) {                                              \
        __syncthreads();                                                                 \
        _Pragma("unroll")                                                                \
        for (int p = 0; p < 4; ++p) {                                                    \
            int r = lr + p * 32;                                                         \
            uint32_t so = SWZ128((uint32_t)(r * 128 + lc * 16));                         \
            size_t goA = (size_t)(m0 + r) * 1024 + kc + lc * 8;                          \
            size_t goB = (size_t)(n0 + r) * 1024 + kc + lc * 8;                          \
            *(uint4*)(smem + SA_HI + so) = *(const uint4*)(Ahi + goA);                   \
            *(uint4*)(smem + SA_LO + so) = *(const uint4*)(Alo + goA);                   \
            *(uint4*)(smem + SB_HI + so) = *(const uint4*)(Bhi + goB);                   \
            *(uint4*)(smem + SB_LO + so) = *(const uint4*)(Blo + goB);                   \
        }                                                                                \
        __syncthreads();                                                                 \
        _Pragma("unroll")                                                                \
        for (int ks = 0; ks < 4; ++ks) {                                                 \
            const int kb = ks * 32;                                                      \
            uint32_t aoff[4], boff[2];                                                   \
            _Pragma("unroll")                                                            \
            for (int i = 0; i < 4; ++i) {                                                \
                int row = wm * 64 + i * 16 + a_row_in;                                   \
                aoff[i] = SWZ128((uint32_t)(row * 128 + kb + a_kb));                     \
            }                                                                            \
            _Pragma("unroll")                                                            \
            for (int jp = 0; jp < 2; ++jp) {                                             \
                int row = wn * 32 + (jp * 2 + b_j2) * 8 + b_row_in;                      \
                boff[jp] = SWZ128((uint32_t)(row * 128 + kb + b_kb));                    \
            }                                                                            \
            uint32_t ah[4][4], al[4][4], bh[4][2], bl[4][2];                             \
            _Pragma("unroll")                                                            \
            for (int i = 0; i < 4; ++i) {                                                \
                ldsm_x4(ah[i][0], ah[i][1], ah[i][2], ah[i][3], sbase + SA_HI + aoff[i]);\
                ldsm_x4(al[i][0], al[i][1], al[i][2], al[i][3], sbase + SA_LO + aoff[i]);\
            }                                                                            \
            _Pragma("unroll")                                                            \
            for (int jp = 0; jp < 2; ++jp) {                                             \
                ldsm_x4(bh[jp * 2][0], bh[jp * 2][1], bh[jp * 2 + 1][0], bh[jp * 2 + 1][1],\
                        sbase + SB_HI + boff[jp]);                                       \
                ldsm_x4(bl[jp * 2][0], bl[jp * 2][1], bl[jp * 2 + 1][0], bl[jp * 2 + 1][1],\
                        sbase + SB_LO + boff[jp]);                                       \
            }                                                                            \
            _Pragma("unroll")                                                            \
            for (int i = 0; i < 4; ++i)                                                  \
                _Pragma("unroll")                                                        \
                for (int j = 0; j < 4; ++j) {                                            \
                    mma_bf16(acc[i][j], ah[i], bh[j]);                                   \
                    mma_bf16(acc[i][j], ah[i], bl[j]);                                   \
                    mma_bf16(acc[i][j], al[i], bh[j]);                                   \
                }                                                                        \
        }                                                                                \
    }

#define GEMM_PROLOGUE()                                          \
    extern __shared__ char smem[];                               \
    const uint32_t sbase = (uint32_t)__cvta_generic_to_shared(smem); \
    const int tid = threadIdx.x;                                 \
    const int w = tid >> 5;                                      \
    const int l = tid & 31;                                      \
    const int wm = w >> 2;                                       \
    const int wn = w & 3;                                        \
    const int m0 = blockIdx.y * 128;                             \
    const int n0 = blockIdx.x * 128;                             \
    const int lr = tid >> 3;                                     \
    const int lc = tid & 7;                                      \
    const int sub = l >> 3;                                      \
    const int a_row_in = ((sub & 1) << 3) + (l & 7);             \
    const int a_kb = (sub >> 1) << 4;                            \
    const int b_j2 = l >> 4;                                     \
    const int b_kb = ((l >> 3) & 1) << 4;                        \
    const int b_row_in = l & 7;                                  \
    float acc[4][4][4];                                          \
    _Pragma("unroll")                                            \
    for (int i = 0; i < 4; ++i)                                  \
        _Pragma("unroll")                                        \
        for (int j = 0; j < 4; ++j)                              \
            _Pragma("unroll")                                    \
            for (int r = 0; r < 4; ++r) acc[i][j][r] = 0.0f;

// ---------------------------------------------------------------------------
// QKV GEMM: [8192,1024] x [3072,1024]^T; epilogue scatters bf16 hi/lo splits
// into q/k/v in [B,H,T,HD] (q pre-scaled by KSCALE).
// ---------------------------------------------------------------------------
__global__ void __launch_bounds__(256, 2) qkv_gemm(
    const __nv_bfloat16* __restrict__ Ahi, const __nv_bfloat16* __restrict__ Alo,
    const __nv_bfloat16* __restrict__ Bhi, const __nv_bfloat16* __restrict__ Blo,
    const float* __restrict__ bias,
    __nv_bfloat16* __restrict__ qhi, __nv_bfloat16* __restrict__ qlo,
    __nv_bfloat16* __restrict__ khi, __nv_bfloat16* __restrict__ klo,
    __nv_bfloat16* __restrict__ vhi, __nv_bfloat16* __restrict__ vlo)
{
    GEMM_PROLOGUE();
    GEMM_MAINLOOP(Ahi, Alo, Bhi, Blo);

    const int gr = l >> 2;
    const int gc = (l & 3) << 1;
#pragma unroll
    for (int i = 0; i < 4; ++i) {
        int mrow = m0 + wm * 64 + i * 16 + gr;
        int bb = mrow >> 11;
        int t = mrow & 2047;
#pragma unroll
        for (int j = 0; j < 4; ++j) {
            int n = n0 + wn * 32 + j * 8 + gc;
            int which = n >> 10;
            int c = n & 1023;
            int h = c >> 6;
            int d = c & 63;
            float2 bv = *(const float2*)(bias + n);
            float sc = (which == 0) ? KSCALE : 1.0f;
            __nv_bfloat16 *dhi, *dlo;
            if (which == 0)      { dhi = qhi; dlo = qlo; }
            else if (which == 1) { dhi = khi; dlo = klo; }
            else                 { dhi = vhi; dlo = vlo; }
            size_t off = (((size_t)bb * HH + h) * TT + t) * HD + d;
#pragma unroll
            for (int rr = 0; rr < 2; ++rr) {   // rows t and t+8
                float v0 = (acc[i][j][rr * 2 + 0] + bv.x) * sc;
                float v1 = (acc[i][j][rr * 2 + 1] + bv.y) * sc;
                __nv_bfloat162 hh = __floats2bfloat162_rn(v0, v1);
                float2 hf = __bfloat1622float2(hh);
                __nv_bfloat162 ll = __floats2bfloat162_rn(v0 - hf.x, v1 - hf.y);
                *(__nv_bfloat162*)(dhi + off + rr * 8 * HD) = hh;
                *(__nv_bfloat162*)(dlo + off + rr * 8 * HD) = ll;
            }
        }
    }
}

// ---------------------------------------------------------------------------
// Output projection: y(split) [8192,1024] x w_out^T(split) + b_out -> fp32 out
// ---------------------------------------------------------------------------
__global__ void __launch_bounds__(256, 2) out_gemm(
    const __nv_bfloat16* __restrict__ Ahi, const __nv_bfloat16* __restrict__ Alo,
    const __nv_bfloat16* __restrict__ Bhi, const __nv_bfloat16* __restrict__ Blo,
    const float* __restrict__ bias, float* __restrict__ C0)
{
    GEMM_PROLOGUE();
    GEMM_MAINLOOP(Ahi, Alo, Bhi, Blo);

    const int gr = l >> 2;
    const int gc = (l & 3) << 1;
#pragma unroll
    for (int i = 0; i < 4; ++i) {
        int mrow = m0 + wm * 64 + i * 16 + gr;
#pragma unroll
        for (int j = 0; j < 4; ++j) {
            int n = n0 + wn * 32 + j * 8 + gc;
            float2 bv = *(const float2*)(bias + n);
            float* ptr = C0 + (size_t)mrow * DD + n;
            float2 v0, v1;
            v0.x = acc[i][j][0] + bv.x;
            v0.y = acc[i][j][1] + bv.y;
            v1.x = acc[i][j][2] + bv.x;
            v1.y = acc[i][j][3] + bv.y;
            *(float2*)ptr = v0;
            *(float2*)(ptr + 8 * DD) = v1;
        }
    }
}

// ---------------------------------------------------------------------------
// Tensor-core flash attention. CTA = 4 warps, q-tile 64 rows, k-tile 64 keys.
// Q (pre-scaled, log2 domain) cached in register fragments across the kt loop.
// S = 3-term bf16 mma; softmax fp32 in registers; P split to bf16 in registers
// (C-fragment == A-fragment layout); PV = 3-term mma, V^T via ldmatrix.trans.
// ---------------------------------------------------------------------------
#define AK_HI 0
#define AK_LO 8192
#define AV_HI 16384
#define AV_LO 24576
#define ATT_SMEM 32768

__global__ void __launch_bounds__(128) fa_kernel(
    const __nv_bfloat16* __restrict__ qhi, const __nv_bfloat16* __restrict__ qlo,
    const __nv_bfloat16* __restrict__ khi, const __nv_bfloat16* __restrict__ klo,
    const __nv_bfloat16* __restrict__ vhi, const __nv_bfloat16* __restrict__ vlo,
    __nv_bfloat16* __restrict__ yhi, __nv_bfloat16* __restrict__ ylo)
{
    __shared__ char smem[ATT_SMEM];
    const uint32_t sbase = (uint32_t)__cvta_generic_to_shared(smem);
    const int tid = threadIdx.x;
    const int w = tid >> 5;
    const int l = tid & 31;
    const int qt = blockIdx.x;
    const int bhid = blockIdx.y;
    const int q0 = qt * 64;
    const size_t base = (size_t)bhid * TT * HD;

    // A-fragment lane mapping
    const int sub = l >> 3;
    const int a_row_in = ((sub & 1) << 3) + (l & 7);
    const int a_kb = (sub >> 1) << 4;
    // B-fragment (non-trans, K) lane mapping
    const int b_j2 = l >> 4;
    const int b_kb = ((l >> 3) & 1) << 4;
    const int b_row_in = l & 7;
    // B-fragment (trans, V) lane mapping
    const int v_key_in = (l & 7) + ((l >> 3) & 1) * 8;
    const int v_n16 = l >> 4;

    // ---- stage Q tile into smem (reuse K buffers), load fragments ----
#pragma unroll
    for (int p = 0; p < 4; ++p) {
        int idx = tid + p * 128;
        int r = idx >> 3;
        int c = idx & 7;
        uint32_t so = SWZ128((uint32_t)(r * 128 + c * 16));
        size_t go = base + (size_t)(q0 + r) * HD + c * 8;
        *(uint4*)(smem + AK_HI + so) = *(const uint4*)(qhi + go);
        *(uint4*)(smem + AK_LO + so) = *(const uint4*)(qlo + go);
    }
    __syncthreads();

    uint32_t qh[4][4], ql[4][4];
#pragma unroll
    for (int ks = 0; ks < 4; ++ks) {
        uint32_t off = SWZ128((uint32_t)((w * 16 + a_row_in) * 128 + ks * 32 + a_kb));
        ldsm_x4(qh[ks][0], qh[ks][1], qh[ks][2], qh[ks][3], sbase + AK_HI + off);
        ldsm_x4(ql[ks][0], ql[ks][1], ql[ks][2], ql[ks][3], sbase + AK_LO + off);
    }

    float o[8][4];
#pragma unroll
    for (int j = 0; j < 8; ++j)
#pragma unroll
        for (int r = 0; r < 4; ++r) o[j][r] = 0.0f;
    float m0r = -CUDART_INF_F, m1r = -CUDART_INF_F;
    float l0r = 0.0f, l1r = 0.0f;

    const int rloc0 = w * 16 + (l >> 2);   // local q row (first of pair)

    for (int kt = 0; kt <= qt; ++kt) {
        __syncthreads();   // Q frags / prev V reads done before overwrite
        const int k0 = kt * 64;
#pragma unroll
        for (int p = 0; p < 4; ++p) {
            int idx = tid + p * 128;
            int r = idx >> 3;
            int c = idx & 7;
            uint32_t so = SWZ128((uint32_t)(r * 128 + c * 16));
            size_t go = base + (size_t)(k0 + r) * HD + c * 8;
            *(uint4*)(smem + AK_HI + so) = *(const uint4*)(khi + go);
            *(uint4*)(smem + AK_LO + so) = *(const uint4*)(klo + go);
            *(uint4*)(smem + AV_HI + so) = *(const uint4*)(vhi + go);
            *(uint4*)(smem + AV_LO + so) = *(const uint4*)(vlo + go);
        }
        __syncthreads();

        // ---- S = Q K^T (3-term), fp32 accum ----
        float s[8][4];
#pragma unroll
        for (int j = 0; j < 8; ++j)
#pragma unroll
            for (int r = 0; r < 4; ++r) s[j][r] = 0.0f;

#pragma unroll
        for (int ks = 0; ks < 4; ++ks) {
            uint32_t kbh[8][2], kbl[8][2];
#pragma unroll
            for (int jp = 0; jp < 4; ++jp) {
                int row = (jp * 2 + b_j2) * 8 + b_row_in;
                uint32_t off = SWZ128((uint32_t)(row * 128 + ks * 32 + b_kb));
                ldsm_x4(kbh[jp * 2][0], kbh[jp * 2][1], kbh[jp * 2 + 1][0], kbh[jp * 2 + 1][1],
                        sbase + AK_HI + off);
                ldsm_x4(kbl[jp * 2][0], kbl[jp * 2][1], kbl[jp * 2 + 1][0], kbl[jp * 2 + 1][1],
                        sbase + AK_LO + off);
            }
#pragma unroll
            for (int j = 0; j < 8; ++j) {
                mma_bf16(s[j], qh[ks], kbh[j]);
                mma_bf16(s[j], qh[ks], kbl[j]);
                mma_bf16(s[j], ql[ks], kbh[j]);
            }
        }

        // ---- causal mask on diagonal tile ----
        if (kt == qt) {
#pragma unroll
            for (int j = 0; j < 8; ++j) {
                int c = j * 8 + ((l & 3) << 1);
                if (c > rloc0)         s[j][0] = -CUDART_INF_F;
                if (c + 1 > rloc0)     s[j][1] = -CUDART_INF_F;
                if (c > rloc0 + 8)     s[j][2] = -CUDART_INF_F;
                if (c + 1 > rloc0 + 8) s[j][3] = -CUDART_INF_F;
            }
        }

        // ---- online softmax (rows rloc0, rloc0+8) ----
        float mx0 = -CUDART_INF_F, mx1 = -CUDART_INF_F;
#pragma unroll
        for (int j = 0; j < 8; ++j) {
            mx0 = fmaxf(mx0, fmaxf(s[j][0], s[j][1]));
            mx1 = fmaxf(mx1, fmaxf(s[j][2], s[j][3]));
        }
        mx0 = fmaxf(mx0, __shfl_xor_sync(0xffffffffu, mx0, 1));
        mx0 = fmaxf(mx0, __shfl_xor_sync(0xffffffffu, mx0, 2));
        mx1 = fmaxf(mx1, __shfl_xor_sync(0xffffffffu, mx1, 1));
        mx1 = fmaxf(mx1, __shfl_xor_sync(0xffffffffu, mx1, 2));

        float mn0 = fmaxf(m0r, mx0);
        float mn1 = fmaxf(m1r, mx1);
        float al0 = exp2f(m0r - mn0);
        float al1 = exp2f(m1r - mn1);
        m0r = mn0; m1r = mn1;

        float rs0 = 0.0f, rs1 = 0.0f;
#pragma unroll
        for (int j = 0; j < 8; ++j) {
            s[j][0] = exp2f(s[j][0] - mn0);
            s[j][1] = exp2f(s[j][1] - mn0);
            s[j][2] = exp2f(s[j][2] - mn1);
            s[j][3] = exp2f(s[j][3] - mn1);
            rs0 += s[j][0] + s[j][1];
            rs1 += s[j][2] + s[j][3];
        }
        rs0 += __shfl_xor_sync(0xffffffffu, rs0, 1);
        rs0 += __shfl_xor_sync(0xffffffffu, rs0, 2);
        rs1 += __shfl_xor_sync(0xffffffffu, rs1, 1);
        rs1 += __shfl_xor_sync(0xffffffffu, rs1, 2);
        l0r = l0r * al0 + rs0;
        l1r = l1r * al1 + rs1;

#pragma unroll
        for (int j = 0; j < 8; ++j) {
            o[j][0] *= al0; o[j][1] *= al0;
            o[j][2] *= al1; o[j][3] *= al1;
        }

        // ---- pack P into bf16 hi/lo A fragments (C layout == A layout) ----
        uint32_t ph[4][4], pl[4][4];
#pragma unroll
        for (int t = 0; t < 4; ++t) {
            const float* s0 = s[2 * t];
            const float* s1 = s[2 * t + 1];
            float2 hf;
            ph[t][0] = packbf(s0[0], s0[1]);
            hf = __bfloat1622float2(*(__nv_bfloat162*)&ph[t][0]);
            pl[t][0] = packbf(s0[0] - hf.x, s0[1] - hf.y);
            ph[t][1] = packbf(s0[2], s0[3]);
            hf = __bfloat1622float2(*(__nv_bfloat162*)&ph[t][1]);
            pl[t][1] = packbf(s0[2] - hf.x, s0[3] - hf.y);
            ph[t][2] = packbf(s1[0], s1[1]);
            hf = __bfloat1622float2(*(__nv_bfloat162*)&ph[t][2]);
            pl[t][2] = packbf(s1[0] - hf.x, s1[1] - hf.y);
            ph[t][3] = packbf(s1[2], s1[3]);
            hf = __bfloat1622float2(*(__nv_bfloat162*)&ph[t][3]);
            pl[t][3] = packbf(s1[2] - hf.x, s1[3] - hf.y);
        }

        // ---- O += P @ V (3-term), V^T fragments via ldmatrix.trans ----
#pragma unroll
        for (int t = 0; t < 4; ++t) {
            uint32_t vbh[8][2], vbl[8][2];
#pragma unroll
            for (int jp = 0; jp < 4; ++jp) {
                int key = t * 16 + v_key_in;
                int n16 = jp * 2 + v_n16;
                uint32_t off = SWZ128((uint32_t)(key * 128 + n16 * 16));
                ldsm_x4_t(vbh[jp * 2][0], vbh[jp * 2][1], vbh[jp * 2 + 1][0], vbh[jp * 2 + 1][1],
                          sbase + AV_HI + off);
                ldsm_x4_t(vbl[jp * 2][0], vbl[jp * 2][1], vbl[jp * 2 + 1][0], vbl[jp * 2 + 1][1],
                          sbase + AV_LO + off);
            }
#pragma unroll
            for (int j = 0; j < 8; ++j) {
                mma_bf16(o[j], ph[t], vbh[j]);
                mma_bf16(o[j], ph[t], vbl[j]);
                mma_bf16(o[j], pl[t], vbh[j]);
            }
        }
    }

    // ---- epilogue: normalize, split to bf16 hi/lo, store y[B,T,D] ----
    const int b = bhid >> 4;
    const int h = bhid & 15;
    const float inv0 = 1.0f / l0r;
    const float inv1 = 1.0f / l1r;
    const int t0 = q0 + rloc0;
#pragma unroll
    for (int j = 0; j < 8; ++j) {
        int col = h * 64 + j * 8 + ((l & 3) << 1);
        size_t off0 = ((size_t)b * TT + t0) * DD + col;
        size_t off1 = ((size_t)b * TT + t0 + 8) * DD + col;
        float v0 = o[j][0] * inv0, v1 = o[j][1] * inv0;
        float v2 = o[j][2] * inv1, v3 = o[j][3] * inv1;
        __nv_bfloat162 h0 = __floats2bfloat162_rn(v0, v1);
        float2 hf0 = __bfloat1622float2(h0);
        __nv_bfloat162 l0 = __floats2bfloat162_rn(v0 - hf0.x, v1 - hf0.y);
        __nv_bfloat162 h1 = __floats2bfloat162_rn(v2, v3);
        float2 hf1 = __bfloat1622float2(h1);
        __nv_bfloat162 l1 = __floats2bfloat162_rn(v2 - hf1.x, v3 - hf1.y);
        *(__nv_bfloat162*)(yhi + off0) = h0;
        *(__nv_bfloat162*)(ylo + off0) = l0;
        *(__nv_bfloat162*)(yhi + off1) = h1;
        *(__nv_bfloat162*)(ylo + off1) = l1;
    }
}

// ---------------------------------------------------------------------------
// Launch pipeline
// ---------------------------------------------------------------------------
extern "C" void kernel_launch(void* const* d_in, const int* in_sizes, int n_in,
                              void* d_out, int out_size)
{
    (void)in_sizes; (void)n_in; (void)out_size;
    const float* x     = (const float*)d_in[0];
    // d_in[1] = causal mask, handled analytically
    const float* w_qkv = (const float*)d_in[2];
    const float* b_qkv = (const float*)d_in[3];
    const float* w_out = (const float*)d_in[4];
    const float* b_out = (const float*)d_in[5];
    float* out = (float*)d_out;

    __nv_bfloat16 *qhi, *qlo, *khi, *klo, *vhi, *vlo;
    __nv_bfloat16 *xhi, *xlo, *wqhi, *wqlo, *wohi, *wolo, *yhi, *ylo;
    cudaGetSymbolAddress((void**)&qhi, g_qhi);
    cudaGetSymbolAddress((void**)&qlo, g_qlo);
    cudaGetSymbolAddress((void**)&khi, g_khi);
    cudaGetSymbolAddress((void**)&klo, g_klo);
    cudaGetSymbolAddress((void**)&vhi, g_vhi);
    cudaGetSymbolAddress((void**)&vlo, g_vlo);
    cudaGetSymbolAddress((void**)&xhi, g_xhi);
    cudaGetSymbolAddress((void**)&xlo, g_xlo);
    cudaGetSymbolAddress((void**)&wqhi, g_wqhi);
    cudaGetSymbolAddress((void**)&wqlo, g_wqlo);
    cudaGetSymbolAddress((void**)&wohi, g_wohi);
    cudaGetSymbolAddress((void**)&wolo, g_wolo);
    cudaGetSymbolAddress((void**)&yhi, g_yhi);
    cudaGetSymbolAddress((void**)&ylo, g_ylo);

    cudaFuncSetAttribute(qkv_gemm, cudaFuncAttributeMaxDynamicSharedMemorySize, GEMM_SMEM);
    cudaFuncSetAttribute(out_gemm, cudaFuncAttributeMaxDynamicSharedMemorySize, GEMM_SMEM);

    const size_t MX = (size_t)BB * TT * DD;  // 8388608

    split_kernel<<<(unsigned)(MX / 4 / 256), 256>>>(x, xhi, xlo);
    splitT_kernel<<<(unsigned)(3 * DD * DD / 256), 256>>>(w_qkv, wqhi, wqlo, 3 * DD);
    splitT_kernel<<<(unsigned)(DD * DD / 256), 256>>>(w_out, wohi, wolo, DD);

    // 1) QKV projection -> bf16 hi/lo q/k/v, [B,H,T,HD], q pre-scaled
    {
        dim3 grid(3 * DD / 128, BB * TT / 128);   // (24, 64)
        qkv_gemm<<<grid, 256, GEMM_SMEM>>>(xhi, xlo, wqhi, wqlo, b_qkv,
                                           qhi, qlo, khi, klo, vhi, vlo);
    }

    // 2) tensor-core causal flash attention -> y bf16 hi/lo
    {
        dim3 grid(TT / 64, BB * HH);
        fa_kernel<<<grid, 128>>>(qhi, qlo, khi, klo, vhi, vlo, yhi, ylo);
    }

    // 3) output projection -> fp32 out
    {
        dim3 grid(DD / 128, BB * TT / 128);       // (8, 64)
        out_gemm<<<grid, 256, GEMM_SMEM>>>(yhi, ylo, wohi, wolo, b_out, out);
    }
}

// round 5
// speedup vs baseline: 3.2041x; 1.0919x over previous
#include <cuda_runtime.h>
#include <cuda_bf16.h>
#include <math_constants.h>
#include <cstddef>
#include <cstdint>

// Problem constants
#define BB 4
#define TT 2048
#define DD 1024
#define HH 16
#define HD 64

#define KSCALE (0.125f * 1.4426950408889634f)   // 1/sqrt(64) * log2(e)

// ---------------------------------------------------------------------------
// Scratch (device globals: allocation-guard-safe)
// ---------------------------------------------------------------------------
__device__ __nv_bfloat16 g_qhi[(size_t)BB * HH * TT * HD];  // [B,H,T,HD], pre-scaled
__device__ __nv_bfloat16 g_qlo[(size_t)BB * HH * TT * HD];
__device__ __nv_bfloat16 g_khi[(size_t)BB * HH * TT * HD];
__device__ __nv_bfloat16 g_klo[(size_t)BB * HH * TT * HD];
__device__ __nv_bfloat16 g_vhi[(size_t)BB * HH * TT * HD];
__device__ __nv_bfloat16 g_vlo[(size_t)BB * HH * TT * HD];

__device__ __nv_bfloat16 g_xhi[(size_t)BB * TT * DD];
__device__ __nv_bfloat16 g_xlo[(size_t)BB * TT * DD];
__device__ __nv_bfloat16 g_wqhi[(size_t)3 * DD * DD];   // w_qkv^T [3072,1024]
__device__ __nv_bfloat16 g_wqlo[(size_t)3 * DD * DD];
__device__ __nv_bfloat16 g_wohi[(size_t)DD * DD];        // w_out^T [1024,1024]
__device__ __nv_bfloat16 g_wolo[(size_t)DD * DD];
__device__ __nv_bfloat16 g_yhi[(size_t)BB * TT * DD];    // attention out, split
__device__ __nv_bfloat16 g_ylo[(size_t)BB * TT * DD];

#define SWZ128(o) ((o) ^ (((o) >> 3) & 0x70))
#define SWZ64(o)  ((o) ^ (((o) >> 3) & 0x30))

// ---------------------------------------------------------------------------
// mma.sync / cp.async helpers (baseline PTX ISA — compiles under compute_103)
// ---------------------------------------------------------------------------
__device__ __forceinline__ void ldsm_x4(uint32_t& r0, uint32_t& r1, uint32_t& r2, uint32_t& r3,
                                        uint32_t addr) {
    asm volatile("ldmatrix.sync.aligned.m8n8.x4.shared.b16 {%0,%1,%2,%3}, [%4];"
                 : "=r"(r0), "=r"(r1), "=r"(r2), "=r"(r3) : "r"(addr));
}
__device__ __forceinline__ void ldsm_x4_t(uint32_t& r0, uint32_t& r1, uint32_t& r2, uint32_t& r3,
                                          uint32_t addr) {
    asm volatile("ldmatrix.sync.aligned.m8n8.x4.trans.shared.b16 {%0,%1,%2,%3}, [%4];"
                 : "=r"(r0), "=r"(r1), "=r"(r2), "=r"(r3) : "r"(addr));
}
__device__ __forceinline__ void mma_bf16(float* d, const uint32_t* a, const uint32_t* b) {
    asm volatile(
        "mma.sync.aligned.m16n8k16.row.col.f32.bf16.bf16.f32 "
        "{%0,%1,%2,%3}, {%4,%5,%6,%7}, {%8,%9}, {%0,%1,%2,%3};"
        : "+f"(d[0]), "+f"(d[1]), "+f"(d[2]), "+f"(d[3])
        : "r"(a[0]), "r"(a[1]), "r"(a[2]), "r"(a[3]), "r"(b[0]), "r"(b[1]));
}
__device__ __forceinline__ uint32_t packbf(float a, float b) {
    __nv_bfloat162 t = __floats2bfloat162_rn(a, b);
    return *(uint32_t*)&t;
}
__device__ __forceinline__ void cp_async16(uint32_t saddr, const void* gptr) {
    asm volatile("cp.async.cg.shared.global [%0], [%1], 16;" :: "r"(saddr), "l"(gptr));
}
#define CP_COMMIT() asm volatile("cp.async.commit_group;" ::: "memory")
#define CP_WAIT1()  asm volatile("cp.async.wait_group 1;" ::: "memory")
#define CP_WAIT0()  asm volatile("cp.async.wait_group 0;" ::: "memory")

// ---------------------------------------------------------------------------
// Split fp32 -> (bf16 hi, bf16 lo). One thread per 4 elems.
// ---------------------------------------------------------------------------
__global__ void split_kernel(const float* __restrict__ x,
                             __nv_bfloat16* __restrict__ hi, __nv_bfloat16* __restrict__ lo)
{
    size_t i = ((size_t)blockIdx.x * blockDim.x + threadIdx.x) * 4;
    float4 v = *(const float4*)(x + i);
    float a[4] = {v.x, v.y, v.z, v.w};
    __nv_bfloat16 h[4], l[4];
#pragma unroll
    for (int j = 0; j < 4; ++j) {
        h[j] = __float2bfloat16(a[j]);
        l[j] = __float2bfloat16(a[j] - __bfloat162float(h[j]));
    }
    *(__nv_bfloat162*)(hi + i)     = __nv_bfloat162(h[0], h[1]);
    *(__nv_bfloat162*)(hi + i + 2) = __nv_bfloat162(h[2], h[3]);
    *(__nv_bfloat162*)(lo + i)     = __nv_bfloat162(l[0], l[1]);
    *(__nv_bfloat162*)(lo + i + 2) = __nv_bfloat162(l[2], l[3]);
}

// Tiled transpose + split: w [1024, N] -> wT hi/lo [N, 1024]. Coalesced both ways.
__global__ void splitT_kernel(const float* __restrict__ w,
                              __nv_bfloat16* __restrict__ hi, __nv_bfloat16* __restrict__ lo, int N)
{
    __shared__ float tile[32][33];
    const int bn = blockIdx.x * 32;   // n offset
    const int bk = blockIdx.y * 32;   // k offset
    const int tx = threadIdx.x;       // 0..31
    const int ty = threadIdx.y;       // 0..7
#pragma unroll
    for (int p = 0; p < 4; ++p)
        tile[ty + p * 8][tx] = w[(size_t)(bk + ty + p * 8) * N + bn + tx];
    __syncthreads();
#pragma unroll
    for (int p = 0; p < 4; ++p) {
        int n = bn + ty + p * 8;
        int k = bk + tx;
        float v = tile[tx][ty + p * 8];
        __nv_bfloat16 h = __float2bfloat16(v);
        hi[(size_t)n * 1024 + k] = h;
        lo[(size_t)n * 1024 + k] = __float2bfloat16(v - __bfloat162float(h));
    }
}

// ---------------------------------------------------------------------------
// GEMM: CTA 128x128, 8 warps 2x4, K-chunk 32, 2-stage cp.async pipeline,
// SW64 swizzle (64B rows). Stage = 32KB: [AHI 8K | ALO 8K | BHI 8K | BLO 8K].
// ---------------------------------------------------------------------------
#define GEMM_SMEM 65536

#define GEMM_PREFETCH(kc, st)                                                 \
    { const uint32_t sb_ = sbase + (st) * 32768;                              \
      _Pragma("unroll")                                                       \
      for (int p = 0; p < 2; ++p) {                                           \
          int idx = tid + p * 256;                                            \
          int r = idx >> 2, c = idx & 3;                                      \
          uint32_t so = SWZ64((uint32_t)(r * 64 + c * 16));                   \
          size_t goA = (size_t)(m0 + r) * 1024 + (kc) * 32 + c * 8;           \
          size_t goB = (size_t)(n0 + r) * 1024 + (kc) * 32 + c * 8;           \
          cp_async16(sb_ + 0     + so, Ahi + goA);                            \
          cp_async16(sb_ + 8192  + so, Alo + goA);                            \
          cp_async16(sb_ + 16384 + so, Bhi + goB);                            \
          cp_async16(sb_ + 24576 + so, Blo + goB);                            \
      } }

#define GEMM_MAINLOOP(Ahi, Alo, Bhi, Blo)                                                 \
    GEMM_PREFETCH(0, 0); CP_COMMIT();                                                     \
    for (int kc = 0; kc < 32; ++kc) {                                                     \
        if (kc + 1 < 32) { GEMM_PREFETCH(kc + 1, (kc + 1) & 1); CP_COMMIT(); CP_WAIT1(); }\
        else { CP_WAIT0(); }                                                              \
        __syncthreads();                                                                  \
        const uint32_t sb = sbase + (kc & 1) * 32768;                                     \
        _Pragma("unroll")                                                                 \
        for (int ks = 0; ks < 2; ++ks) {                                                  \
            const int kb = ks * 32;                                                       \
            uint32_t aoff[4], boff[2];                                                    \
            _Pragma("unroll")                                                             \
            for (int i = 0; i < 4; ++i) {                                                 \
                int row = wm * 64 + i * 16 + a_row_in;                                    \
                aoff[i] = SWZ64((uint32_t)(row * 64 + kb + a_kb));                        \
            }                                                                             \
            _Pragma("unroll")                                                             \
            for (int jp = 0; jp < 2; ++jp) {                                              \
                int row = wn * 32 + (jp * 2 + b_j2) * 8 + b_row_in;                       \
                boff[jp] = SWZ64((uint32_t)(row * 64 + kb + b_kb));                       \
            }                                                                             \
            uint32_t ah[4][4], al[4][4], bh[4][2], bl[4][2];                              \
            _Pragma("unroll")                                                             \
            for (int i = 0; i < 4; ++i) {                                                 \
                ldsm_x4(ah[i][0], ah[i][1], ah[i][2], ah[i][3], sb + 0    + aoff[i]);     \
                ldsm_x4(al[i][0], al[i][1], al[i][2], al[i][3], sb + 8192 + aoff[i]);     \
            }                                                                             \
            _Pragma("unroll")                                                             \
            for (int jp = 0; jp < 2; ++jp) {                                              \
                ldsm_x4(bh[jp * 2][0], bh[jp * 2][1], bh[jp * 2 + 1][0], bh[jp * 2 + 1][1],\
                        sb + 16384 + boff[jp]);                                           \
                ldsm_x4(bl[jp * 2][0], bl[jp * 2][1], bl[jp * 2 + 1][0], bl[jp * 2 + 1][1],\
                        sb + 24576 + boff[jp]);                                           \
            }                                                                             \
            _Pragma("unroll")                                                             \
            for (int i = 0; i < 4; ++i)                                                   \
                _Pragma("unroll")                                                         \
                for (int j = 0; j < 4; ++j) {                                             \
                    mma_bf16(acc[i][j], ah[i], bh[j]);                                    \
                    mma_bf16(acc[i][j], ah[i], bl[j]);                                    \
                    mma_bf16(acc[i][j], al[i], bh[j]);                                    \
                }                                                                         \
        }                                                                                 \
        __syncthreads();                                                                  \
    }

#define GEMM_PROLOGUE()                                          \
    extern __shared__ char smem[];                               \
    const uint32_t sbase = (uint32_t)__cvta_generic_to_shared(smem); \
    const int tid = threadIdx.x;                                 \
    const int w = tid >> 5;                                      \
    const int l = tid & 31;                                      \
    const int wm = w >> 2;                                       \
    const int wn = w & 3;                                        \
    const int m0 = blockIdx.y * 128;                             \
    const int n0 = blockIdx.x * 128;                             \
    const int sub = l >> 3;                                      \
    const int a_row_in = ((sub & 1) << 3) + (l & 7);             \
    const int a_kb = (sub >> 1) << 4;                            \
    const int b_j2 = l >> 4;                                     \
    const int b_kb = ((l >> 3) & 1) << 4;                        \
    const int b_row_in = l & 7;                                  \
    float acc[4][4][4];                                          \
    _Pragma("unroll")                                            \
    for (int i = 0; i < 4; ++i)                                  \
        _Pragma("unroll")                                        \
        for (int j = 0; j < 4; ++j)                              \
            _Pragma("unroll")                                    \
            for (int r = 0; r < 4; ++r) acc[i][j][r] = 0.0f;

// ---------------------------------------------------------------------------
// QKV GEMM: epilogue scatters bf16 hi/lo splits into q/k/v (q pre-scaled).
// ---------------------------------------------------------------------------
__global__ void __launch_bounds__(256, 2) qkv_gemm(
    const __nv_bfloat16* __restrict__ Ahi, const __nv_bfloat16* __restrict__ Alo,
    const __nv_bfloat16* __restrict__ Bhi, const __nv_bfloat16* __restrict__ Blo,
    const float* __restrict__ bias,
    __nv_bfloat16* __restrict__ qhi, __nv_bfloat16* __restrict__ qlo,
    __nv_bfloat16* __restrict__ khi, __nv_bfloat16* __restrict__ klo,
    __nv_bfloat16* __restrict__ vhi, __nv_bfloat16* __restrict__ vlo)
{
    GEMM_PROLOGUE();
    GEMM_MAINLOOP(Ahi, Alo, Bhi, Blo);

    const int gr = l >> 2;
    const int gc = (l & 3) << 1;
#pragma unroll
    for (int i = 0; i < 4; ++i) {
        int mrow = m0 + wm * 64 + i * 16 + gr;
        int bb = mrow >> 11;
        int t = mrow & 2047;
#pragma unroll
        for (int j = 0; j < 4; ++j) {
            int n = n0 + wn * 32 + j * 8 + gc;
            int which = n >> 10;
            int c = n & 1023;
            int h = c >> 6;
            int d = c & 63;
            float2 bv = *(const float2*)(bias + n);
            float sc = (which == 0) ? KSCALE : 1.0f;
            __nv_bfloat16 *dhi, *dlo;
            if (which == 0)      { dhi = qhi; dlo = qlo; }
            else if (which == 1) { dhi = khi; dlo = klo; }
            else                 { dhi = vhi; dlo = vlo; }
            size_t off = (((size_t)bb * HH + h) * TT + t) * HD + d;
#pragma unroll
            for (int rr = 0; rr < 2; ++rr) {   // rows t and t+8
                float v0 = (acc[i][j][rr * 2 + 0] + bv.x) * sc;
                float v1 = (acc[i][j][rr * 2 + 1] + bv.y) * sc;
                __nv_bfloat162 hh = __floats2bfloat162_rn(v0, v1);
                float2 hf = __bfloat1622float2(hh);
                __nv_bfloat162 ll = __floats2bfloat162_rn(v0 - hf.x, v1 - hf.y);
                *(__nv_bfloat162*)(dhi + off + rr * 8 * HD) = hh;
                *(__nv_bfloat162*)(dlo + off + rr * 8 * HD) = ll;
            }
        }
    }
}

// ---------------------------------------------------------------------------
// Output projection: y(split) x w_out^T(split) + b_out -> fp32 out
// ---------------------------------------------------------------------------
__global__ void __launch_bounds__(256, 2) out_gemm(
    const __nv_bfloat16* __restrict__ Ahi, const __nv_bfloat16* __restrict__ Alo,
    const __nv_bfloat16* __restrict__ Bhi, const __nv_bfloat16* __restrict__ Blo,
    const float* __restrict__ bias, float* __restrict__ C0)
{
    GEMM_PROLOGUE();
    GEMM_MAINLOOP(Ahi, Alo, Bhi, Blo);

    const int gr = l >> 2;
    const int gc = (l & 3) << 1;
#pragma unroll
    for (int i = 0; i < 4; ++i) {
        int mrow = m0 + wm * 64 + i * 16 + gr;
#pragma unroll
        for (int j = 0; j < 4; ++j) {
            int n = n0 + wn * 32 + j * 8 + gc;
            float2 bv = *(const float2*)(bias + n);
            float* ptr = C0 + (size_t)mrow * DD + n;
            float2 v0, v1;
            v0.x = acc[i][j][0] + bv.x;
            v0.y = acc[i][j][1] + bv.y;
            v1.x = acc[i][j][2] + bv.x;
            v1.y = acc[i][j][3] + bv.y;
            *(float2*)ptr = v0;
            *(float2*)(ptr + 8 * DD) = v1;
        }
    }
}

// ---------------------------------------------------------------------------
// Tensor-core flash attention with cp.async double-buffered K/V tiles.
// CTA = 4 warps, q-tile 64 rows, k-tile 64 keys, SW128 (128B rows).
// Stage = 32KB: [KHI 8K | KLO 8K | VHI 8K | VLO 8K], 2 stages = 64KB dynamic.
// Q staged into stage-1 region before the loop.
// ---------------------------------------------------------------------------
#define ATT_SMEM 65536

#define FA_PREFETCH(kt, st)                                                   \
    { const uint32_t sb_ = sbase + (st) * 32768;                              \
      _Pragma("unroll")                                                       \
      for (int p = 0; p < 4; ++p) {                                           \
          int idx = tid + p * 128;                                            \
          int r = idx >> 3, c = idx & 7;                                      \
          uint32_t so = SWZ128((uint32_t)(r * 128 + c * 16));                 \
          size_t go = base + (size_t)((kt) * 64 + r) * HD + c * 8;            \
          cp_async16(sb_ + 0     + so, khi + go);                             \
          cp_async16(sb_ + 8192  + so, klo + go);                             \
          cp_async16(sb_ + 16384 + so, vhi + go);                             \
          cp_async16(sb_ + 24576 + so, vlo + go);                             \
      } }

__global__ void __launch_bounds__(128) fa_kernel(
    const __nv_bfloat16* __restrict__ qhi, const __nv_bfloat16* __restrict__ qlo,
    const __nv_bfloat16* __restrict__ khi, const __nv_bfloat16* __restrict__ klo,
    const __nv_bfloat16* __restrict__ vhi, const __nv_bfloat16* __restrict__ vlo,
    __nv_bfloat16* __restrict__ yhi, __nv_bfloat16* __restrict__ ylo)
{
    extern __shared__ char smem[];
    const uint32_t sbase = (uint32_t)__cvta_generic_to_shared(smem);
    const int tid = threadIdx.x;
    const int w = tid >> 5;
    const int l = tid & 31;
    const int qt = blockIdx.x;
    const int bhid = blockIdx.y;
    const int q0 = qt * 64;
    const size_t base = (size_t)bhid * TT * HD;

    // A-fragment lane mapping
    const int sub = l >> 3;
    const int a_row_in = ((sub & 1) << 3) + (l & 7);
    const int a_kb = (sub >> 1) << 4;
    // B-fragment (non-trans, K) lane mapping
    const int b_j2 = l >> 4;
    const int b_kb = ((l >> 3) & 1) << 4;
    const int b_row_in = l & 7;
    // B-fragment (trans, V) lane mapping
    const int v_key_in = (l & 7) + ((l >> 3) & 1) * 8;
    const int v_n16 = l >> 4;

    // ---- stage Q tile into stage-1 region, load fragments ----
#pragma unroll
    for (int p = 0; p < 4; ++p) {
        int idx = tid + p * 128;
        int r = idx >> 3;
        int c = idx & 7;
        uint32_t so = SWZ128((uint32_t)(r * 128 + c * 16));
        size_t go = base + (size_t)(q0 + r) * HD + c * 8;
        *(uint4*)(smem + 32768 + 0    + so) = *(const uint4*)(qhi + go);
        *(uint4*)(smem + 32768 + 8192 + so) = *(const uint4*)(qlo + go);
    }
    __syncthreads();

    uint32_t qh[4][4], ql[4][4];
#pragma unroll
    for (int ks = 0; ks < 4; ++ks) {
        uint32_t off = SWZ128((uint32_t)((w * 16 + a_row_in) * 128 + ks * 32 + a_kb));
        ldsm_x4(qh[ks][0], qh[ks][1], qh[ks][2], qh[ks][3], sbase + 32768 + 0    + off);
        ldsm_x4(ql[ks][0], ql[ks][1], ql[ks][2], ql[ks][3], sbase + 32768 + 8192 + off);
    }

    // prefetch kt=0 into stage 0
    FA_PREFETCH(0, 0); CP_COMMIT();
    __syncthreads();   // all warps done reading Q from stage-1 region

    float o[8][4];
#pragma unroll
    for (int j = 0; j < 8; ++j)
#pragma unroll
        for (int r = 0; r < 4; ++r) o[j][r] = 0.0f;
    float m0r = -CUDART_INF_F, m1r = -CUDART_INF_F;
    float l0r = 0.0f, l1r = 0.0f;

    const int rloc0 = w * 16 + (l >> 2);   // local q row (first of pair)

    for (int kt = 0; kt <= qt; ++kt) {
        if (kt + 1 <= qt) { FA_PREFETCH(kt + 1, (kt + 1) & 1); CP_COMMIT(); CP_WAIT1(); }
        else { CP_WAIT0(); }
        __syncthreads();
        const uint32_t sb = sbase + (kt & 1) * 32768;

        // ---- S = Q K^T (3-term), fp32 accum ----
        float s[8][4];
#pragma unroll
        for (int j = 0; j < 8; ++j)
#pragma unroll
            for (int r = 0; r < 4; ++r) s[j][r] = 0.0f;

#pragma unroll
        for (int ks = 0; ks < 4; ++ks) {
            uint32_t kbh[8][2], kbl[8][2];
#pragma unroll
            for (int jp = 0; jp < 4; ++jp) {
                int row = (jp * 2 + b_j2) * 8 + b_row_in;
                uint32_t off = SWZ128((uint32_t)(row * 128 + ks * 32 + b_kb));
                ldsm_x4(kbh[jp * 2][0], kbh[jp * 2][1], kbh[jp * 2 + 1][0], kbh[jp * 2 + 1][1],
                        sb + 0 + off);
                ldsm_x4(kbl[jp * 2][0], kbl[jp * 2][1], kbl[jp * 2 + 1][0], kbl[jp * 2 + 1][1],
                        sb + 8192 + off);
            }
#pragma unroll
            for (int j = 0; j < 8; ++j) {
                mma_bf16(s[j], qh[ks], kbh[j]);
                mma_bf16(s[j], qh[ks], kbl[j]);
                mma_bf16(s[j], ql[ks], kbh[j]);
            }
        }

        // ---- causal mask on diagonal tile ----
        if (kt == qt) {
#pragma unroll
            for (int j = 0; j < 8; ++j) {
                int c = j * 8 + ((l & 3) << 1);
                if (c > rloc0)         s[j][0] = -CUDART_INF_F;
                if (c + 1 > rloc0)     s[j][1] = -CUDART_INF_F;
                if (c > rloc0 + 8)     s[j][2] = -CUDART_INF_F;
                if (c + 1 > rloc0 + 8) s[j][3] = -CUDART_INF_F;
            }
        }

        // ---- online softmax (rows rloc0, rloc0+8) ----
        float mx0 = -CUDART_INF_F, mx1 = -CUDART_INF_F;
#pragma unroll
        for (int j = 0; j < 8; ++j) {
            mx0 = fmaxf(mx0, fmaxf(s[j][0], s[j][1]));
            mx1 = fmaxf(mx1, fmaxf(s[j][2], s[j][3]));
        }
        mx0 = fmaxf(mx0, __shfl_xor_sync(0xffffffffu, mx0, 1));
        mx0 = fmaxf(mx0, __shfl_xor_sync(0xffffffffu, mx0, 2));
        mx1 = fmaxf(mx1, __shfl_xor_sync(0xffffffffu, mx1, 1));
        mx1 = fmaxf(mx1, __shfl_xor_sync(0xffffffffu, mx1, 2));

        float mn0 = fmaxf(m0r, mx0);
        float mn1 = fmaxf(m1r, mx1);
        float al0 = exp2f(m0r - mn0);
        float al1 = exp2f(m1r - mn1);
        m0r = mn0; m1r = mn1;

        float rs0 = 0.0f, rs1 = 0.0f;
#pragma unroll
        for (int j = 0; j < 8; ++j) {
            s[j][0] = exp2f(s[j][0] - mn0);
            s[j][1] = exp2f(s[j][1] - mn0);
            s[j][2] = exp2f(s[j][2] - mn1);
            s[j][3] = exp2f(s[j][3] - mn1);
            rs0 += s[j][0] + s[j][1];
            rs1 += s[j][2] + s[j][3];
        }
        rs0 += __shfl_xor_sync(0xffffffffu, rs0, 1);
        rs0 += __shfl_xor_sync(0xffffffffu, rs0, 2);
        rs1 += __shfl_xor_sync(0xffffffffu, rs1, 1);
        rs1 += __shfl_xor_sync(0xffffffffu, rs1, 2);
        l0r = l0r * al0 + rs0;
        l1r = l1r * al1 + rs1;

#pragma unroll
        for (int j = 0; j < 8; ++j) {
            o[j][0] *= al0; o[j][1] *= al0;
            o[j][2] *= al1; o[j][3] *= al1;
        }

        // ---- pack P into bf16 hi/lo A fragments (C layout == A layout) ----
        uint32_t ph[4][4], pl[4][4];
#pragma unroll
        for (int t = 0; t < 4; ++t) {
            const float* s0 = s[2 * t];
            const float* s1 = s[2 * t + 1];
            float2 hf;
            ph[t][0] = packbf(s0[0], s0[1]);
            hf = __bfloat1622float2(*(__nv_bfloat162*)&ph[t][0]);
            pl[t][0] = packbf(s0[0] - hf.x, s0[1] - hf.y);
            ph[t][1] = packbf(s0[2], s0[3]);
            hf = __bfloat1622float2(*(__nv_bfloat162*)&ph[t][1]);
            pl[t][1] = packbf(s0[2] - hf.x, s0[3] - hf.y);
            ph[t][2] = packbf(s1[0], s1[1]);
            hf = __bfloat1622float2(*(__nv_bfloat162*)&ph[t][2]);
            pl[t][2] = packbf(s1[0] - hf.x, s1[1] - hf.y);
            ph[t][3] = packbf(s1[2], s1[3]);
            hf = __bfloat1622float2(*(__nv_bfloat162*)&ph[t][3]);
            pl[t][3] = packbf(s1[2] - hf.x, s1[3] - hf.y);
        }

        // ---- O += P @ V (3-term), V^T fragments via ldmatrix.trans ----
#pragma unroll
        for (int t = 0; t < 4; ++t) {
            uint32_t vbh[8][2], vbl[8][2];
#pragma unroll
            for (int jp = 0; jp < 4; ++jp) {
                int key = t * 16 + v_key_in;
                int n16 = jp * 2 + v_n16;
                uint32_t off = SWZ128((uint32_t)(key * 128 + n16 * 16));
                ldsm_x4_t(vbh[jp * 2][0], vbh[jp * 2][1], vbh[jp * 2 + 1][0], vbh[jp * 2 + 1][1],
                          sb + 16384 + off);
                ldsm_x4_t(vbl[jp * 2][0], vbl[jp * 2][1], vbl[jp * 2 + 1][0], vbl[jp * 2 + 1][1],
                          sb + 24576 + off);
            }
#pragma unroll
            for (int j = 0; j < 8; ++j) {
                mma_bf16(o[j], ph[t], vbh[j]);
                mma_bf16(o[j], ph[t], vbl[j]);
                mma_bf16(o[j], pl[t], vbh[j]);
            }
        }
        __syncthreads();
    }

    // ---- epilogue: normalize, split to bf16 hi/lo, store y[B,T,D] ----
    const int b = bhid >> 4;
    const int h = bhid & 15;
    const float inv0 = 1.0f / l0r;
    const float inv1 = 1.0f / l1r;
    const int t0 = q0 + rloc0;
#pragma unroll
    for (int j = 0; j < 8; ++j) {
        int col = h * 64 + j * 8 + ((l & 3) << 1);
        size_t off0 = ((size_t)b * TT + t0) * DD + col;
        size_t off1 = ((size_t)b * TT + t0 + 8) * DD + col;
        float v0 = o[j][0] * inv0, v1 = o[j][1] * inv0;
        float v2 = o[j][2] * inv1, v3 = o[j][3] * inv1;
        __nv_bfloat162 h0 = __floats2bfloat162_rn(v0, v1);
        float2 hf0 = __bfloat1622float2(h0);
        __nv_bfloat162 l0 = __floats2bfloat162_rn(v0 - hf0.x, v1 - hf0.y);
        __nv_bfloat162 h1 = __floats2bfloat162_rn(v2, v3);
        float2 hf1 = __bfloat1622float2(h1);
        __nv_bfloat162 l1 = __floats2bfloat162_rn(v2 - hf1.x, v3 - hf1.y);
        *(__nv_bfloat162*)(yhi + off0) = h0;
        *(__nv_bfloat162*)(ylo + off0) = l0;
        *(__nv_bfloat162*)(yhi + off1) = h1;
        *(__nv_bfloat162*)(ylo + off1) = l1;
    }
}

// ---------------------------------------------------------------------------
// Launch pipeline
// ---------------------------------------------------------------------------
extern "C" void kernel_launch(void* const* d_in, const int* in_sizes, int n_in,
                              void* d_out, int out_size)
{
    (void)in_sizes; (void)n_in; (void)out_size;
    const float* x     = (const float*)d_in[0];
    // d_in[1] = causal mask, handled analytically
    const float* w_qkv = (const float*)d_in[2];
    const float* b_qkv = (const float*)d_in[3];
    const float* w_out = (const float*)d_in[4];
    const float* b_out = (const float*)d_in[5];
    float* out = (float*)d_out;

    __nv_bfloat16 *qhi, *qlo, *khi, *klo, *vhi, *vlo;
    __nv_bfloat16 *xhi, *xlo, *wqhi, *wqlo, *wohi, *wolo, *yhi, *ylo;
    cudaGetSymbolAddress((void**)&qhi, g_qhi);
    cudaGetSymbolAddress((void**)&qlo, g_qlo);
    cudaGetSymbolAddress((void**)&khi, g_khi);
    cudaGetSymbolAddress((void**)&klo, g_klo);
    cudaGetSymbolAddress((void**)&vhi, g_vhi);
    cudaGetSymbolAddress((void**)&vlo, g_vlo);
    cudaGetSymbolAddress((void**)&xhi, g_xhi);
    cudaGetSymbolAddress((void**)&xlo, g_xlo);
    cudaGetSymbolAddress((void**)&wqhi, g_wqhi);
    cudaGetSymbolAddress((void**)&wqlo, g_wqlo);
    cudaGetSymbolAddress((void**)&wohi, g_wohi);
    cudaGetSymbolAddress((void**)&wolo, g_wolo);
    cudaGetSymbolAddress((void**)&yhi, g_yhi);
    cudaGetSymbolAddress((void**)&ylo, g_ylo);

    cudaFuncSetAttribute(qkv_gemm, cudaFuncAttributeMaxDynamicSharedMemorySize, GEMM_SMEM);
    cudaFuncSetAttribute(out_gemm, cudaFuncAttributeMaxDynamicSharedMemorySize, GEMM_SMEM);
    cudaFuncSetAttribute(fa_kernel, cudaFuncAttributeMaxDynamicSharedMemorySize, ATT_SMEM);

    const size_t MX = (size_t)BB * TT * DD;  // 8388608

    split_kernel<<<(unsigned)(MX / 4 / 256), 256>>>(x, xhi, xlo);
    {
        dim3 grid(3 * DD / 32, DD / 32);
        splitT_kernel<<<grid, dim3(32, 8)>>>(w_qkv, wqhi, wqlo, 3 * DD);
    }
    {
        dim3 grid(DD / 32, DD / 32);
        splitT_kernel<<<grid, dim3(32, 8)>>>(w_out, wohi, wolo, DD);
    }

    // 1) QKV projection -> bf16 hi/lo q/k/v, [B,H,T,HD], q pre-scaled
    {
        dim3 grid(3 * DD / 128, BB * TT / 128);   // (24, 64)
        qkv_gemm<<<grid, 256, GEMM_SMEM>>>(xhi, xlo, wqhi, wqlo, b_qkv,
                                           qhi, qlo, khi, klo, vhi, vlo);
    }

    // 2) tensor-core causal flash attention -> y bf16 hi/lo
    {
        dim3 grid(TT / 64, BB * HH);
        fa_kernel<<<grid, 128, ATT_SMEM>>>(qhi, qlo, khi, klo, vhi, vlo, yhi, ylo);
    }

    // 3) output projection -> fp32 out
    {
        dim3 grid(DD / 128, BB * TT / 128);       // (8, 64)
        out_gemm<<<grid, 256, GEMM_SMEM>>>(yhi, ylo, wohi, wolo, b_out, out);
    }
}